// round 3
// baseline (speedup 1.0000x reference)
#include <cuda_runtime.h>
#include <cuda_fp16.h>
#include <cstdint>
#include <cstddef>

// ---------------------------------------------------------------------------
// FastKAN layer as ONE fp16 GEMM (mma.sync path; tcgen05 unavailable because
// the harness compiles PTX at compute_103, which lacks the "a" features):
//   out[b,j] = sum_{i,s} A[b, i*36+s] * B[j, i*36+s]
//   s in [0,35): cubic B-spline basis coeff c=s;  s==35: silu(x_norm) slot,
//   with B[j, i*36+35] = base_scale[i,j].
// ---------------------------------------------------------------------------

#define BATCH   4096
#define INDIM   1024
#define OUTDIM  1024
#define NC      35
#define SLOTS   36
#define KTOT    (INDIM * SLOTS)      // 36864

#define BM      128
#define BN      128
#define BK      64                   // fp16 per K-chunk (128B rows)
#define STAGES  4
#define ITERS   (KTOT / BK)          // 576
#define TILEB   (BM * BK * 2)        // 16384 bytes per operand per stage
#define STGB    (2 * TILEB)          // 32768
#define SMEM_TOTAL (STAGES * STGB)   // 131072

__device__ __align__(128) __half g_A[(size_t)BATCH  * KTOT];  // ~302 MB
__device__ __align__(128) __half g_B[(size_t)OUTDIM * KTOT];  //  ~74 MB

// ------------------------------- helpers -----------------------------------
__device__ __forceinline__ uint32_t smem_u32(const void* p) {
    uint32_t a;
    asm("{ .reg .u64 t; cvta.to.shared.u64 t, %1; cvt.u32.u64 %0, t; }" : "=r"(a) : "l"(p));
    return a;
}
__device__ __forceinline__ void cp16(uint32_t s, const void* g) {
    asm volatile("cp.async.cg.shared.global [%0], [%1], 16;" :: "r"(s), "l"(g) : "memory");
}
#define CP_COMMIT() asm volatile("cp.async.commit_group;" ::: "memory")
#define CP_WAIT(n)  asm volatile("cp.async.wait_group %0;" :: "n"(n) : "memory")
#define SWZ(off) ((off) ^ (((off) >> 3) & 0x70))

// ---------------------------------------------------------------------------
// prep_B: pack spline_weight [i][j][c] + base_scale [i][j] into
//         g_B[j][i*36 + s] fp16 (K-major B operand).
// ---------------------------------------------------------------------------
__global__ void prep_B(const float* __restrict__ W, const float* __restrict__ bs) {
    int kk = blockIdx.x * 256 + threadIdx.x;   // [0, 36864)
    int j  = blockIdx.y;
    int i  = kk / SLOTS;
    int s  = kk - i * SLOTS;
    float v = (s < NC) ? W[((size_t)i * OUTDIM + j) * NC + s]
                       : bs[(size_t)i * OUTDIM + j];
    g_B[(size_t)j * KTOT + kk] = __float2half_rn(v);
}

// ---------------------------------------------------------------------------
// prep_A: per (b,i), 4 active cubic B-spline taps + silu slot 35 into
//         g_A[b][i*36 + s] fp16. Staged via SMEM (dynamic tap index without
//         register spills), then coalesced block copy to global.
// ---------------------------------------------------------------------------
__global__ void prep_A(const float* __restrict__ x, const float* __restrict__ grid) {
    __shared__ __half sbuf[256 * SLOTS];
    int tid = threadIdx.x;
    size_t pair0 = (size_t)blockIdx.x * 256;
    float xv = x[pair0 + tid];
    float xn = fminf(fmaxf(xv, -0.99f), 0.99f);

    half2* my2 = (half2*)(sbuf + tid * SLOTS);   // 36 halves = 72B, 4B-aligned
    #pragma unroll
    for (int q = 0; q < SLOTS / 2; q++) my2[q] = __floats2half2_rn(0.f, 0.f);
    __half* my = sbuf + tid * SLOTS;

    const float invh = 17.0f;                     // (NC-1)/2
    float t = (xn + 1.0f) * invh;
    int cl = (int)floorf(t) - 1;                  // active c in [cl, cl+3]
    #pragma unroll
    for (int q = 0; q < 4; q++) {
        int c = cl + q;
        if (c >= 0 && c < NC) {
            float d = fabsf(xn - grid[c]) * invh;
            float inner = 0.66666667f - d * d + d * d * d * 0.5f;
            float tt = 2.0f - d;
            float outer = tt * tt * tt * (1.0f / 6.0f);
            float v = (d < 1.0f) ? inner : ((d < 2.0f) ? outer : 0.0f);
            my[c] = __float2half_rn(v);
        }
    }
    my[NC] = __float2half_rn(xn / (1.0f + __expf(-xn)));
    __syncthreads();

    // 256*36 halves = 4608 u32 words, coalesced copy out
    const uint32_t* s4 = (const uint32_t*)sbuf;
    uint32_t* g4 = (uint32_t*)(g_A + pair0 * SLOTS);
    #pragma unroll
    for (int w = 0; w < 4608 / 256; w++) g4[w * 256 + tid] = s4[w * 256 + tid];
}

// ---------------------------------------------------------------------------
// kan_gemm: 128x128 CTA tile, K=36864, 4-stage cp.async + mma.sync m16n8k16.
// 8 warps (2 m x 4 n), warp tile 64x32.
// ---------------------------------------------------------------------------
__global__ void __launch_bounds__(256, 1) kan_gemm(float* __restrict__ out) {
    extern __shared__ __align__(1024) char smem[];
    uint32_t sb = smem_u32(smem);
    int tid = threadIdx.x;
    int wid = tid >> 5;
    int lid = tid & 31;
    int tn  = blockIdx.x;       // [0,8)
    int tm  = blockIdx.y;       // [0,32)
    int wm  = wid & 1;          // 2 warps along M
    int wn  = wid >> 1;         // 4 warps along N

    const __half* gA = g_A + (size_t)(tm * BM) * KTOT;
    const __half* gB = g_B + (size_t)(tn * BN) * KTOT;

    // per-thread copy coordinates (4 chunks of 16B for A, 4 for B per stage)
    int crow[4], ccol[4];
    uint32_t cdst[4];
    #pragma unroll
    for (int q = 0; q < 4; q++) {
        int ci = tid + q * 256;
        crow[q] = ci >> 3;
        ccol[q] = (ci & 7) * 8;                      // halves
        uint32_t off = crow[q] * 128 + (ci & 7) * 16;
        cdst[q] = SWZ(off);
    }

    float acc[4][4][4];
    #pragma unroll
    for (int a = 0; a < 4; a++)
        #pragma unroll
        for (int b = 0; b < 4; b++)
            #pragma unroll
            for (int c = 0; c < 4; c++) acc[a][b][c] = 0.f;

    // stage copy
    auto copy_stage = [&](int it) {
        int s = it & (STAGES - 1);
        uint32_t sa  = sb + s * STGB;
        uint32_t sbm = sa + TILEB;
        size_t k0 = (size_t)it * BK;
        #pragma unroll
        for (int q = 0; q < 4; q++)
            cp16(sa + cdst[q], gA + (size_t)crow[q] * KTOT + k0 + ccol[q]);
        #pragma unroll
        for (int q = 0; q < 4; q++)
            cp16(sbm + cdst[q], gB + (size_t)crow[q] * KTOT + k0 + ccol[q]);
        CP_COMMIT();
    };

    copy_stage(0); copy_stage(1); copy_stage(2);

    // precomputed smem fragment addresses (swizzled), advanced per stage
    // A: row = wm*64 + mt*16 + (lid&15), kbyte = ks*32 + (lid>>4)*16
    // B: row = wn*32 + nt*8  + (lid&7),  kbyte = ks*32 + ((lid>>3)&1)*16
    for (int k = 0; k < ITERS; k++) {
        CP_WAIT(2);
        __syncthreads();
        if (k + 3 < ITERS) copy_stage(k + 3); else CP_COMMIT();

        uint32_t sa  = sb + (k & (STAGES - 1)) * STGB;
        uint32_t sbm = sa + TILEB;

        #pragma unroll
        for (int ks = 0; ks < 4; ks++) {
            uint32_t af[4][4];
            uint32_t bf[4][2];
            #pragma unroll
            for (int mt = 0; mt < 4; mt++) {
                uint32_t row = wm * 64 + mt * 16 + (lid & 15);
                uint32_t off = row * 128 + ks * 32 + (lid >> 4) * 16;
                uint32_t addr = sa + SWZ(off);
                asm volatile(
                    "ldmatrix.sync.aligned.m8n8.x4.shared.b16 {%0,%1,%2,%3}, [%4];"
                    : "=r"(af[mt][0]), "=r"(af[mt][1]), "=r"(af[mt][2]), "=r"(af[mt][3])
                    : "r"(addr));
            }
            #pragma unroll
            for (int nt = 0; nt < 4; nt++) {
                uint32_t row = wn * 32 + nt * 8 + (lid & 7);
                uint32_t off = row * 128 + ks * 32 + ((lid >> 3) & 1) * 16;
                uint32_t addr = sbm + SWZ(off);
                asm volatile(
                    "ldmatrix.sync.aligned.m8n8.x2.shared.b16 {%0,%1}, [%2];"
                    : "=r"(bf[nt][0]), "=r"(bf[nt][1])
                    : "r"(addr));
            }
            #pragma unroll
            for (int mt = 0; mt < 4; mt++)
                #pragma unroll
                for (int nt = 0; nt < 4; nt++) {
                    asm volatile(
                        "mma.sync.aligned.m16n8k16.row.col.f32.f16.f16.f32 "
                        "{%0,%1,%2,%3}, {%4,%5,%6,%7}, {%8,%9}, {%0,%1,%2,%3};"
                        : "+f"(acc[mt][nt][0]), "+f"(acc[mt][nt][1]),
                          "+f"(acc[mt][nt][2]), "+f"(acc[mt][nt][3])
                        : "r"(af[mt][0]), "r"(af[mt][1]), "r"(af[mt][2]), "r"(af[mt][3]),
                          "r"(bf[nt][0]), "r"(bf[nt][1]));
                }
        }
    }
    CP_WAIT(0);

    // Epilogue: mma accum layout -> gmem
    #pragma unroll
    for (int mt = 0; mt < 4; mt++) {
        int r0 = tm * BM + wm * 64 + mt * 16 + (lid >> 2);
        #pragma unroll
        for (int nt = 0; nt < 4; nt++) {
            int c0 = tn * BN + wn * 32 + nt * 8 + (lid & 3) * 2;
            *(float2*)(out + (size_t)r0 * OUTDIM + c0) =
                make_float2(acc[mt][nt][0], acc[mt][nt][1]);
            *(float2*)(out + (size_t)(r0 + 8) * OUTDIM + c0) =
                make_float2(acc[mt][nt][2], acc[mt][nt][3]);
        }
    }
}

// ---------------------------------------------------------------------------
extern "C" void kernel_launch(void* const* d_in, const int* in_sizes, int n_in,
                              void* d_out, int out_size) {
    const float* x    = (const float*)d_in[0];
    const float* W    = (const float*)d_in[1];
    const float* bs   = (const float*)d_in[2];
    const float* grid = (const float*)d_in[3];
    float* out = (float*)d_out;

    cudaFuncSetAttribute(kan_gemm, cudaFuncAttributeMaxDynamicSharedMemorySize, SMEM_TOTAL);

    prep_B<<<dim3(KTOT / 256, OUTDIM), 256>>>(W, bs);
    prep_A<<<(BATCH * INDIM) / 256, 256>>>(x, grid);
    kan_gemm<<<dim3(OUTDIM / BN, BATCH / BM), 256, SMEM_TOTAL>>>(out);
}

// round 4
// speedup vs baseline: 1.2360x; 1.2360x over previous
#include <cuda_runtime.h>
#include <cuda_fp16.h>
#include <cstdint>
#include <cstddef>

// ---------------------------------------------------------------------------
// FastKAN layer as ONE fp16 GEMM (mma.sync path; tcgen05 unavailable: harness
// compiles PTX at compute_103 which lacks the "a"-suffix features):
//   out[b,j] = sum_{i,s} A[b, i*36+s] * B[j, i*36+s]
//   s in [0,35): cubic B-spline basis coeff c=s;  s==35: silu(x_norm) slot,
//   with B[j, i*36+35] = base_scale[i,j].
// Round 4: 256x128 CTA tile (one wave, 128 CTAs), 4x2 warp grid, warp tile
// 64x64; L2 traffic 4.83 -> 3.54 GB; prep_B j-unrolled x4.
// ---------------------------------------------------------------------------

#define BATCH   4096
#define INDIM   1024
#define OUTDIM  1024
#define NC      35
#define SLOTS   36
#define KTOT    (INDIM * SLOTS)      // 36864

#define BM      256
#define BN      128
#define BK      64                   // fp16 per K-chunk (128B rows)
#define STAGES  4
#define ITERS   (KTOT / BK)          // 576
#define ATILEB  (BM * BK * 2)        // 32768 bytes
#define BTILEB  (BN * BK * 2)        // 16384 bytes
#define STGB    (ATILEB + BTILEB)    // 49152
#define SMEM_TOTAL (STAGES * STGB)   // 196608

__device__ __align__(128) __half g_A[(size_t)BATCH  * KTOT];  // ~302 MB
__device__ __align__(128) __half g_B[(size_t)OUTDIM * KTOT];  //  ~74 MB

// ------------------------------- helpers -----------------------------------
__device__ __forceinline__ uint32_t smem_u32(const void* p) {
    uint32_t a;
    asm("{ .reg .u64 t; cvta.to.shared.u64 t, %1; cvt.u32.u64 %0, t; }" : "=r"(a) : "l"(p));
    return a;
}
__device__ __forceinline__ void cp16(uint32_t s, const void* g) {
    asm volatile("cp.async.cg.shared.global [%0], [%1], 16;" :: "r"(s), "l"(g) : "memory");
}
#define CP_COMMIT() asm volatile("cp.async.commit_group;" ::: "memory")
#define CP_WAIT(n)  asm volatile("cp.async.wait_group %0;" :: "n"(n) : "memory")
#define SWZ(off) ((off) ^ (((off) >> 3) & 0x70))

// ---------------------------------------------------------------------------
// prep_B: pack spline_weight [i][j][c] + base_scale [i][j] into
//         g_B[j][i*36 + s] fp16 (K-major B operand). 4 j's per thread (MLP).
// ---------------------------------------------------------------------------
__global__ void prep_B(const float* __restrict__ W, const float* __restrict__ bs) {
    int kk = blockIdx.x * 256 + threadIdx.x;   // [0, 36864)
    int j0 = blockIdx.y * 4;
    int i  = kk / SLOTS;
    int s  = kk - i * SLOTS;
    #pragma unroll
    for (int q = 0; q < 4; q++) {
        int j = j0 + q;
        float v = (s < NC) ? W[((size_t)i * OUTDIM + j) * NC + s]
                           : bs[(size_t)i * OUTDIM + j];
        g_B[(size_t)j * KTOT + kk] = __float2half_rn(v);
    }
}

// ---------------------------------------------------------------------------
// prep_A: per (b,i), 4 active cubic B-spline taps + silu slot 35 into
//         g_A[b][i*36 + s] fp16. Staged via SMEM (dynamic tap index without
//         register spills), then coalesced block copy to global.
// ---------------------------------------------------------------------------
__global__ void prep_A(const float* __restrict__ x, const float* __restrict__ grid) {
    __shared__ __half sbuf[256 * SLOTS];
    int tid = threadIdx.x;
    size_t pair0 = (size_t)blockIdx.x * 256;
    float xv = x[pair0 + tid];
    float xn = fminf(fmaxf(xv, -0.99f), 0.99f);

    half2* my2 = (half2*)(sbuf + tid * SLOTS);   // 36 halves = 72B, 4B-aligned
    #pragma unroll
    for (int q = 0; q < SLOTS / 2; q++) my2[q] = __floats2half2_rn(0.f, 0.f);
    __half* my = sbuf + tid * SLOTS;

    const float invh = 17.0f;                     // (NC-1)/2
    float t = (xn + 1.0f) * invh;
    int cl = (int)floorf(t) - 1;                  // active c in [cl, cl+3]
    #pragma unroll
    for (int q = 0; q < 4; q++) {
        int c = cl + q;
        if (c >= 0 && c < NC) {
            float d = fabsf(xn - grid[c]) * invh;
            float inner = 0.66666667f - d * d + d * d * d * 0.5f;
            float tt = 2.0f - d;
            float outer = tt * tt * tt * (1.0f / 6.0f);
            float v = (d < 1.0f) ? inner : ((d < 2.0f) ? outer : 0.0f);
            my[c] = __float2half_rn(v);
        }
    }
    my[NC] = __float2half_rn(xn / (1.0f + __expf(-xn)));
    __syncthreads();

    // 256*36 halves = 4608 u32 words, coalesced copy out
    const uint32_t* s4 = (const uint32_t*)sbuf;
    uint32_t* g4 = (uint32_t*)(g_A + pair0 * SLOTS);
    #pragma unroll
    for (int w = 0; w < 4608 / 256; w++) g4[w * 256 + tid] = s4[w * 256 + tid];
}

// ---------------------------------------------------------------------------
// kan_gemm: 256x128 CTA tile, K=36864, 4-stage cp.async + mma.sync m16n8k16.
// 8 warps as 4(M) x 2(N); warp tile 64x64. One wave: 128 CTAs.
// ---------------------------------------------------------------------------
__global__ void __launch_bounds__(256, 1) kan_gemm(float* __restrict__ out) {
    extern __shared__ __align__(1024) char smem[];
    uint32_t sb = smem_u32(smem);
    int tid = threadIdx.x;
    int wid = tid >> 5;
    int lid = tid & 31;
    int tn  = blockIdx.x;       // [0,8)
    int tm  = blockIdx.y;       // [0,16)
    int wm  = wid & 3;          // 4 warps along M
    int wn  = wid >> 2;         // 2 warps along N

    const __half* gA = g_A + (size_t)(tm * BM) * KTOT;
    const __half* gB = g_B + (size_t)(tn * BN) * KTOT;

    // per-thread copy coordinates: A = 8 chunks of 16B, B = 4 chunks
    int arow[8]; uint32_t acol[8], adst[8];
    #pragma unroll
    for (int q = 0; q < 8; q++) {
        int ci = tid + q * 256;
        arow[q] = ci >> 3;
        acol[q] = (ci & 7) * 8;
        uint32_t off = (uint32_t)arow[q] * 128 + (ci & 7) * 16;
        adst[q] = SWZ(off);
    }
    int brow[4]; uint32_t bcol[4], bdst[4];
    #pragma unroll
    for (int q = 0; q < 4; q++) {
        int ci = tid + q * 256;
        brow[q] = ci >> 3;
        bcol[q] = (ci & 7) * 8;
        uint32_t off = (uint32_t)brow[q] * 128 + (ci & 7) * 16;
        bdst[q] = SWZ(off);
    }

    float acc[4][8][4];
    #pragma unroll
    for (int a = 0; a < 4; a++)
        #pragma unroll
        for (int b = 0; b < 8; b++)
            #pragma unroll
            for (int c = 0; c < 4; c++) acc[a][b][c] = 0.f;

    auto copy_stage = [&](int it) {
        int s = it & (STAGES - 1);
        uint32_t sa  = sb + s * STGB;
        uint32_t sbm = sa + ATILEB;
        size_t k0 = (size_t)it * BK;
        #pragma unroll
        for (int q = 0; q < 8; q++)
            cp16(sa + adst[q], gA + (size_t)arow[q] * KTOT + k0 + acol[q]);
        #pragma unroll
        for (int q = 0; q < 4; q++)
            cp16(sbm + bdst[q], gB + (size_t)brow[q] * KTOT + k0 + bcol[q]);
        CP_COMMIT();
    };

    copy_stage(0); copy_stage(1); copy_stage(2);

    for (int k = 0; k < ITERS; k++) {
        CP_WAIT(2);
        __syncthreads();
        if (k + 3 < ITERS) copy_stage(k + 3); else CP_COMMIT();

        uint32_t sa  = sb + (k & (STAGES - 1)) * STGB;
        uint32_t sbm = sa + ATILEB;

        #pragma unroll
        for (int ks = 0; ks < 4; ks++) {
            uint32_t af[4][4];
            uint32_t bf[8][2];
            #pragma unroll
            for (int mt = 0; mt < 4; mt++) {
                uint32_t row = wm * 64 + mt * 16 + (lid & 15);
                uint32_t off = row * 128 + ks * 32 + (lid >> 4) * 16;
                uint32_t addr = sa + SWZ(off);
                asm volatile(
                    "ldmatrix.sync.aligned.m8n8.x4.shared.b16 {%0,%1,%2,%3}, [%4];"
                    : "=r"(af[mt][0]), "=r"(af[mt][1]), "=r"(af[mt][2]), "=r"(af[mt][3])
                    : "r"(addr));
            }
            #pragma unroll
            for (int nt = 0; nt < 8; nt++) {
                uint32_t row = wn * 64 + nt * 8 + (lid & 7);
                uint32_t off = row * 128 + ks * 32 + ((lid >> 3) & 1) * 16;
                uint32_t addr = sbm + SWZ(off);
                asm volatile(
                    "ldmatrix.sync.aligned.m8n8.x2.shared.b16 {%0,%1}, [%2];"
                    : "=r"(bf[nt][0]), "=r"(bf[nt][1])
                    : "r"(addr));
            }
            #pragma unroll
            for (int mt = 0; mt < 4; mt++)
                #pragma unroll
                for (int nt = 0; nt < 8; nt++) {
                    asm volatile(
                        "mma.sync.aligned.m16n8k16.row.col.f32.f16.f16.f32 "
                        "{%0,%1,%2,%3}, {%4,%5,%6,%7}, {%8,%9}, {%0,%1,%2,%3};"
                        : "+f"(acc[mt][nt][0]), "+f"(acc[mt][nt][1]),
                          "+f"(acc[mt][nt][2]), "+f"(acc[mt][nt][3])
                        : "r"(af[mt][0]), "r"(af[mt][1]), "r"(af[mt][2]), "r"(af[mt][3]),
                          "r"(bf[nt][0]), "r"(bf[nt][1]));
                }
        }
    }
    CP_WAIT(0);

    // Epilogue: mma accum layout -> gmem
    #pragma unroll
    for (int mt = 0; mt < 4; mt++) {
        int r0 = tm * BM + wm * 64 + mt * 16 + (lid >> 2);
        #pragma unroll
        for (int nt = 0; nt < 8; nt++) {
            int c0 = tn * BN + wn * 64 + nt * 8 + (lid & 3) * 2;
            *(float2*)(out + (size_t)r0 * OUTDIM + c0) =
                make_float2(acc[mt][nt][0], acc[mt][nt][1]);
            *(float2*)(out + (size_t)(r0 + 8) * OUTDIM + c0) =
                make_float2(acc[mt][nt][2], acc[mt][nt][3]);
        }
    }
}

// ---------------------------------------------------------------------------
extern "C" void kernel_launch(void* const* d_in, const int* in_sizes, int n_in,
                              void* d_out, int out_size) {
    const float* x    = (const float*)d_in[0];
    const float* W    = (const float*)d_in[1];
    const float* bs   = (const float*)d_in[2];
    const float* grid = (const float*)d_in[3];
    float* out = (float*)d_out;

    cudaFuncSetAttribute(kan_gemm, cudaFuncAttributeMaxDynamicSharedMemorySize, SMEM_TOTAL);

    prep_B<<<dim3(KTOT / 256, OUTDIM / 4), 256>>>(W, bs);
    prep_A<<<(BATCH * INDIM) / 256, 256>>>(x, grid);
    kan_gemm<<<dim3(OUTDIM / BN, BATCH / BM), 256, SMEM_TOTAL>>>(out);
}